// round 10
// baseline (speedup 1.0000x reference)
#include <cuda_runtime.h>
#include <cstdint>

// Problem dims
#define NB 128   // batch (GEMM M)
#define NI 256   // in_features (GEMM K)
#define NH 128   // H (grid)
#define NO 32    // OUT (GEMM N)

#define DROW 260  // padded row stride in 32-bit words (conflict-free)

// Scratch: w[b][h][o]  (fully overwritten every launch -> no init needed)
__device__ float g_w[NB * NH * NO];

static __device__ __forceinline__ uint32_t cvt_tf32(float f) {
    uint32_t u;
    asm("cvt.rna.tf32.f32 %0, %1;" : "=r"(u) : "f"(f));
    return u;
}

static __device__ __forceinline__ void mma_tf32(
    float d[4], uint32_t a0, uint32_t a1, uint32_t a2, uint32_t a3,
    uint32_t b0, uint32_t b1)
{
    asm volatile(
        "mma.sync.aligned.m16n8k8.row.col.f32.tf32.tf32.f32 "
        "{%0,%1,%2,%3}, {%4,%5,%6,%7}, {%8,%9}, {%0,%1,%2,%3};"
        : "+f"(d[0]), "+f"(d[1]), "+f"(d[2]), "+f"(d[3])
        : "r"(a0), "r"(a1), "r"(a2), "r"(a3), "r"(b0), "r"(b1));
}

// ---------------------------------------------------------------------------
// Kernel A: ONE CTA per h, 512 threads. Classic HMMA TF32 GEMM:
//   D[b,o] = sum_i A[b,i]*B[o,i],  A=(chi-x)^2, B=sigma_psi^2 (tf32-rna)
//   then g_w[b][h][o] = 1/(D + sigma_eps^2)
// Warp layout: 16 warps = 8 M-tiles (16 rows) x 2 N-halves (16 cols).
// Per warp: 32 K-steps of k=8, 2 mma.m16n8k8 per step.
// ---------------------------------------------------------------------------
__global__ __launch_bounds__(512, 1) void order1_main(
    const float* __restrict__ input,      // [NB][NI]
    const float* __restrict__ sigma_psi,  // [NI][NH][NO]
    const float* __restrict__ chi,        // [NI][NH]
    const float* __restrict__ sigma_eps)  // [NH][NO]
{
    extern __shared__ uint32_t usmem[];
    uint32_t* As = usmem;               // [NB][DROW] tf32 bits
    uint32_t* Bs = usmem + NB * DROW;   // [NO][DROW] tf32 bits

    const int h    = blockIdx.x;
    const int tid  = threadIdx.x;
    const int wid  = tid >> 5;
    const int lane = tid & 31;

    // ---- Phase 1: Bs[o][i] = tf32(sigma_psi[i,h,o]^2) ----
    {
        const float4* sp4 = reinterpret_cast<const float4*>(sigma_psi);
#pragma unroll
        for (int k = 0; k < 4; k++) {
            int idx4 = tid + k * 512;          // 0..2047
            int i  = idx4 >> 3;
            int o4 = idx4 & 7;
            float4 v = sp4[(i * NH + h) * 8 + o4];
            Bs[(o4 * 4 + 0) * DROW + i] = cvt_tf32(v.x * v.x);
            Bs[(o4 * 4 + 1) * DROW + i] = cvt_tf32(v.y * v.y);
            Bs[(o4 * 4 + 2) * DROW + i] = cvt_tf32(v.z * v.z);
            Bs[(o4 * 4 + 3) * DROW + i] = cvt_tf32(v.w * v.w);
        }
    }

    // ---- Phase 2: As[b][i] = tf32((chi[i,h]-x[b,i])^2), STS.128 ----
    {
        const int iq = tid & 63;   // i-quad
        const int bb = tid >> 6;   // 0..7 (uniform within warp)
        const int i  = iq * 4;
        const float c0 = chi[(i + 0) * NH + h];
        const float c1 = chi[(i + 1) * NH + h];
        const float c2 = chi[(i + 2) * NH + h];
        const float c3 = chi[(i + 3) * NH + h];
#pragma unroll 4
        for (int k = 0; k < 16; k++) {
            const int b = bb + 8 * k;
            float4 x4 = *reinterpret_cast<const float4*>(input + b * NI + i);
            float d0 = c0 - x4.x, d1 = c1 - x4.y, d2 = c2 - x4.z, d3 = c3 - x4.w;
            uint4 u;
            u.x = cvt_tf32(d0 * d0);
            u.y = cvt_tf32(d1 * d1);
            u.z = cvt_tf32(d2 * d2);
            u.w = cvt_tf32(d3 * d3);
            *reinterpret_cast<uint4*>(As + b * DROW + i) = u;
        }
    }
    __syncthreads();

    // ---- MMA phase ----
    const int m  = wid >> 1;      // M-tile: rows m*16 .. m*16+15
    const int nh = wid & 1;       // N-half: cols nh*16 .. nh*16+15
    const int g  = lane >> 2;     // group id
    const int c  = lane & 3;      // thread-in-group

    const uint32_t* pA0 = As + (m * 16 + g) * DROW + c;       // rows g
    const uint32_t* pA1 = pA0 + 8 * DROW;                     // rows g+8
    const uint32_t* pB0 = Bs + (nh * 16 + g) * DROW + c;      // tile0 cols
    const uint32_t* pB1 = pB0 + 8 * DROW;                     // tile1 cols

    float acc0[4] = {0.f, 0.f, 0.f, 0.f};
    float acc1[4] = {0.f, 0.f, 0.f, 0.f};

#pragma unroll 8
    for (int t = 0; t < 32; t++) {
        const int koff = t * 8;
        // A fragment (16x8): banks 4*g + c -> conflict-free
        uint32_t a0 = pA0[koff];
        uint32_t a1 = pA1[koff];
        uint32_t a2 = pA0[koff + 4];
        uint32_t a3 = pA1[koff + 4];
        // B fragments for 2 n-tiles
        uint32_t b00 = pB0[koff];
        uint32_t b01 = pB0[koff + 4];
        uint32_t b10 = pB1[koff];
        uint32_t b11 = pB1[koff + 4];
        mma_tf32(acc0, a0, a1, a2, a3, b00, b01);
        mma_tf32(acc1, a0, a1, a2, a3, b10, b11);
    }

    // ---- Epilogue: w = 1/(s + eps^2), store g_w[b][h][o] ----
    {
        const int r0 = m * 16 + g;       // D row for acc[0],acc[1]
        const int r1 = r0 + 8;           // D row for acc[2],acc[3]
        const int o0 = nh * 16 + c * 2;  // tile0 col pair
        const int o1 = o0 + 8;           // tile1 col pair

        const float* se = sigma_eps + h * NO;
        float e00 = se[o0],     e01 = se[o0 + 1];
        float e10 = se[o1],     e11 = se[o1 + 1];
        e00 *= e00; e01 *= e01; e10 *= e10; e11 *= e11;

        float* g0 = g_w + (r0 * NH + h) * NO;
        float* g1 = g_w + (r1 * NH + h) * NO;

        *reinterpret_cast<float2*>(g0 + o0) =
            make_float2(__fdividef(1.f, acc0[0] + e00),
                        __fdividef(1.f, acc0[1] + e01));
        *reinterpret_cast<float2*>(g1 + o0) =
            make_float2(__fdividef(1.f, acc0[2] + e00),
                        __fdividef(1.f, acc0[3] + e01));
        *reinterpret_cast<float2*>(g0 + o1) =
            make_float2(__fdividef(1.f, acc1[0] + e10),
                        __fdividef(1.f, acc1[1] + e11));
        *reinterpret_cast<float2*>(g1 + o1) =
            make_float2(__fdividef(1.f, acc1[2] + e10),
                        __fdividef(1.f, acc1[3] + e11));
    }
}

// ---------------------------------------------------------------------------
// Kernel B: CTA per b, 512 threads. One coalesced float4 sweep of the 16KB
// g_w row + eta, butterfly h-reduction, tiny smem combine.  (round-8 proven)
// ---------------------------------------------------------------------------
__global__ __launch_bounds__(512) void order1_finish(
    const float* __restrict__ eta,        // [NH][NO]
    const float* __restrict__ mu_phi,     // [NO]
    const float* __restrict__ sigma_phi,  // [NO]
    float* __restrict__ out, int out_size)
{
    __shared__ float4 sA[16 * 8];
    __shared__ float4 sB[16 * 8];

    const int b = blockIdx.x;
    const int t = threadIdx.x;
    const int wid = t >> 5;
    const int l = t & 31;

    const float4* row4 = reinterpret_cast<const float4*>(g_w + b * NH * NO);
    const float4* eta4 = reinterpret_cast<const float4*>(eta);

    float4 sw  = make_float4(0.f, 0.f, 0.f, 0.f);
    float4 swe = make_float4(0.f, 0.f, 0.f, 0.f);
#pragma unroll
    for (int rep = 0; rep < 2; rep++) {
        int idx = t + rep * 512;   // seg = idx&7 constant over rep
        float4 w4 = row4[idx];
        float4 e4 = eta4[idx];
        sw.x += w4.x; sw.y += w4.y; sw.z += w4.z; sw.w += w4.w;
        swe.x += w4.x * e4.x; swe.y += w4.y * e4.y;
        swe.z += w4.z * e4.z; swe.w += w4.w * e4.w;
    }

#pragma unroll
    for (int m = 8; m <= 16; m <<= 1) {
        sw.x += __shfl_xor_sync(0xffffffffu, sw.x, m);
        sw.y += __shfl_xor_sync(0xffffffffu, sw.y, m);
        sw.z += __shfl_xor_sync(0xffffffffu, sw.z, m);
        sw.w += __shfl_xor_sync(0xffffffffu, sw.w, m);
        swe.x += __shfl_xor_sync(0xffffffffu, swe.x, m);
        swe.y += __shfl_xor_sync(0xffffffffu, swe.y, m);
        swe.z += __shfl_xor_sync(0xffffffffu, swe.z, m);
        swe.w += __shfl_xor_sync(0xffffffffu, swe.w, m);
    }
    if (l < 8) {
        sA[wid * 8 + l] = sw;
        sB[wid * 8 + l] = swe;
    }
    __syncthreads();

    if (t < 8) {
        float4 a = sA[t], bb = sB[t];
#pragma unroll
        for (int k = 1; k < 16; k++) {
            float4 a2 = sA[k * 8 + t], b2 = sB[k * 8 + t];
            a.x += a2.x; a.y += a2.y; a.z += a2.z; a.w += a2.w;
            bb.x += b2.x; bb.y += b2.y; bb.z += b2.z; bb.w += b2.w;
        }
        const int o = t * 4;
        float4 mp = *reinterpret_cast<const float4*>(mu_phi + o);
        float4 sp = *reinterpret_cast<const float4*>(sigma_phi + o);
        float swa[4]  = {a.x, a.y, a.z, a.w};
        float swea[4] = {bb.x, bb.y, bb.z, bb.w};
        float mpa[4]  = {mp.x, mp.y, mp.z, mp.w};
        float spa[4]  = {sp.x, sp.y, sp.z, sp.w};
        float pm[4], ps[4];
#pragma unroll
        for (int cc = 0; cc < 4; cc++) {
            float sp2 = spa[cc] * spa[cc];
            float inv = __fdividef(1.0f, fmaf(sp2, swa[cc], 1.0f));
            pm[cc] = (mpa[cc] + sp2 * swea[cc]) * inv;
            ps[cc] = sp2 * inv;
        }
        *reinterpret_cast<float4*>(out + b * NO + o) =
            make_float4(pm[0], pm[1], pm[2], pm[3]);
        if (out_size >= 2 * NB * NO)
            *reinterpret_cast<float4*>(out + NB * NO + b * NO + o) =
                make_float4(ps[0], ps[1], ps[2], ps[3]);
    }
}

extern "C" void kernel_launch(void* const* d_in, const int* in_sizes, int n_in,
                              void* d_out, int out_size) {
    const float* input     = (const float*)d_in[0];
    const float* sigma_psi = (const float*)d_in[1];
    const float* chi       = (const float*)d_in[2];
    const float* sigma_eps = (const float*)d_in[3];
    const float* eta       = (const float*)d_in[4];
    const float* mu_phi    = (const float*)d_in[5];
    const float* sigma_phi = (const float*)d_in[6];

    const int smemA = (NB + NO) * DROW * (int)sizeof(uint32_t);  // 166400 B
    cudaFuncSetAttribute(order1_main,
                         cudaFuncAttributeMaxDynamicSharedMemorySize, smemA);

    order1_main<<<NH, 512, smemA>>>(input, sigma_psi, chi, sigma_eps);
    order1_finish<<<NB, 512>>>(eta, mu_phi, sigma_phi, (float*)d_out, out_size);
}